// round 7
// baseline (speedup 1.0000x reference)
#include <cuda_runtime.h>

#define NS   50000
#define NT   50000
#define NN   100000
#define HN   50000          // needed half per conv
#define D    128
#define NEG  0.2f

// ---------------- scratch (device globals; no allocation allowed) ----------
__device__ float    g_x[(size_t)NN * D];      // transformed node features (51.2 MB)
__device__ float    g_agg[(size_t)HN * D];    // per-conv aggregation (25.6 MB, reused)
__device__ float    g_as1[NN], g_ad1[NN], g_as2[NN], g_ad2[NN];
__device__ float    g_w1s[D], g_w1d[D], g_w2s[D], g_w2d[D];
__device__ unsigned g_emax[HN];
__device__ float    g_denom[HN];
__device__ int      g_is64;

// ---------------- helpers ---------------------------------------------------
__device__ __forceinline__ unsigned fenc(float f) {
    unsigned u = __float_as_uint(f);
    return (u & 0x80000000u) ? ~u : (u | 0x80000000u);
}
__device__ __forceinline__ float fdec(unsigned u) {
    return __uint_as_float((u & 0x80000000u) ? (u ^ 0x80000000u) : ~u);
}
__device__ __forceinline__ float lrelu(float v) { return v >= 0.f ? v : NEG * v; }

// ---------------- index width detection -------------------------------------
__global__ void k_detect(const int* __restrict__ p) {
    if (threadIdx.x == 0) {
        int all0 = 1;
        #pragma unroll
        for (int i = 1; i < 128; i += 2) all0 &= (p[i] == 0);
        g_is64 = all0;   // int64 little-endian: odd 32-bit words are high halves == 0
    }
}

// ---------------- w-vectors: wv = W^T @ a  ----------------------------------
__global__ void k_wvec(const float* __restrict__ W1, const float* __restrict__ a1s,
                       const float* __restrict__ a1d,
                       const float* __restrict__ W2, const float* __restrict__ a2s,
                       const float* __restrict__ a2d) {
    int j = threadIdx.x;
    float s1 = 0.f, d1 = 0.f, s2 = 0.f, d2 = 0.f;
    for (int k = 0; k < D; k++) {
        float w1 = W1[k * D + j], w2 = W2[k * D + j];
        s1 = fmaf(w1, a1s[k], s1); d1 = fmaf(w1, a1d[k], d1);
        s2 = fmaf(w2, a2s[k], s2); d2 = fmaf(w2, a2d[k], d2);
    }
    g_w1s[j] = s1; g_w1d[j] = d1; g_w2s[j] = s2; g_w2d[j] = d2;
}

// ---------------- generic GEMM: out[r,k] = act(bias[k] + (in[r]*scale[r]) . W[k,:])
// rows must be a multiple of 25. blockDim = 128 (k = column).
__global__ __launch_bounds__(128) void k_gemm(
    const float* __restrict__ in, const float* __restrict__ W,
    const float* __restrict__ bias, const float* __restrict__ denom,
    float* __restrict__ out, int relu)
{
    __shared__ float Wt_s[64 * 129];   // transposed W half, pad 129 -> conflict-free
    __shared__ float xs_s[25 * 128];

    const int k = threadIdx.x;
    const int row0 = blockIdx.x * 25;

    // load 25 input rows (optionally scaled by 1/(denom+eps))
    for (int t = threadIdx.x; t < 25 * 128; t += 128) {
        int r = t >> 7;
        float v = in[(size_t)(row0 + r) * D + (t & 127)];
        if (denom) v *= 1.0f / (denom[row0 + r] + 1e-16f);
        xs_s[t] = v;
    }

    float acc[25];
    #pragma unroll
    for (int r = 0; r < 25; r++) acc[r] = 0.f;

    for (int half = 0; half < 2; half++) {
        __syncthreads();
        // stage W[:, half*64 : half*64+64] transposed
        #pragma unroll 4
        for (int t = threadIdx.x; t < 64 * 128; t += 128) {
            int kk = t >> 6, j = t & 63;
            Wt_s[j * 129 + kk] = W[kk * D + (half << 6) + j];
        }
        __syncthreads();

        const float4* xb = (const float4*)xs_s;
        const int jb = half << 4;   // float4 offset within a row
        for (int j4 = 0; j4 < 16; j4++) {
            float w0 = Wt_s[(j4 * 4 + 0) * 129 + k];
            float w1 = Wt_s[(j4 * 4 + 1) * 129 + k];
            float w2 = Wt_s[(j4 * 4 + 2) * 129 + k];
            float w3 = Wt_s[(j4 * 4 + 3) * 129 + k];
            #pragma unroll
            for (int r = 0; r < 25; r++) {
                float4 xv = xb[r * 32 + jb + j4];
                acc[r] = fmaf(xv.x, w0, acc[r]);
                acc[r] = fmaf(xv.y, w1, acc[r]);
                acc[r] = fmaf(xv.z, w2, acc[r]);
                acc[r] = fmaf(xv.w, w3, acc[r]);
            }
        }
    }

    float b = bias ? bias[k] : 0.f;
    #pragma unroll
    for (int r = 0; r < 25; r++) {
        float v = acc[r] + b;
        if (relu) v = fmaxf(v, 0.f);
        out[(size_t)(row0 + r) * D + k] = v;
    }
}

// ---------------- attention logits: a = x . wv (warp per node) -------------
__global__ void k_att() {
    int n = (blockIdx.x * blockDim.x + threadIdx.x) >> 5;
    int lane = threadIdx.x & 31;
    if (n >= NN) return;
    float4 xv = ((const float4*)g_x)[(size_t)n * 32 + lane];
    float4 w;
    w = ((const float4*)g_w1s)[lane];
    float p1 = xv.x * w.x + xv.y * w.y + xv.z * w.z + xv.w * w.w;
    w = ((const float4*)g_w1d)[lane];
    float p2 = xv.x * w.x + xv.y * w.y + xv.z * w.z + xv.w * w.w;
    w = ((const float4*)g_w2s)[lane];
    float p3 = xv.x * w.x + xv.y * w.y + xv.z * w.z + xv.w * w.w;
    w = ((const float4*)g_w2d)[lane];
    float p4 = xv.x * w.x + xv.y * w.y + xv.z * w.z + xv.w * w.w;
    #pragma unroll
    for (int off = 16; off; off >>= 1) {
        p1 += __shfl_down_sync(0xffffffffu, p1, off);
        p2 += __shfl_down_sync(0xffffffffu, p2, off);
        p3 += __shfl_down_sync(0xffffffffu, p3, off);
        p4 += __shfl_down_sync(0xffffffffu, p4, off);
    }
    if (lane == 0) { g_as1[n] = p1; g_ad1[n] = p2; g_as2[n] = p3; g_ad2[n] = p4; }
}

// ---------------- self-loop pass 1: initializes e_max -----------------------
__global__ void k_self1(int base, const float* __restrict__ as, const float* __restrict__ ad) {
    int i = blockIdx.x * blockDim.x + threadIdx.x;
    if (i >= HN) return;
    int g = base + i;
    g_emax[i] = fenc(lrelu(as[g] + ad[g]));
}

// ---------------- edge pass 1: atomicMax on encoded floats ------------------
__global__ void k_emax(const void* __restrict__ idx, int sOff, int dOff, int E,
                       int sAdd, int dAdd, int base,
                       const float* __restrict__ as, const float* __restrict__ ad) {
    int e = blockIdx.x * blockDim.x + threadIdx.x;
    if (e >= E) return;
    long long s, d;
    if (g_is64) {
        s = ((const long long*)idx)[sOff + e];
        d = ((const long long*)idx)[dOff + e];
    } else {
        s = ((const int*)idx)[sOff + e];
        d = ((const int*)idx)[dOff + e];
    }
    s += sAdd; d += dAdd;
    int di = (int)d - base;
    if ((unsigned)di >= (unsigned)HN) return;   // prune: dst row never read
    float v = lrelu(as[s] + ad[d]);
    atomicMax(&g_emax[di], fenc(v));
}

// ---------------- self-loop pass 2: initializes denom & agg -----------------
__global__ void k_self2(int base, const float* __restrict__ as, const float* __restrict__ ad) {
    int i = (blockIdx.x * blockDim.x + threadIdx.x) >> 5;
    int lane = threadIdx.x & 31;
    if (i >= HN) return;
    int g = base + i;
    float e = lrelu(as[g] + ad[g]);
    float w = __expf(e - fdec(g_emax[i]));
    if (lane == 0) g_denom[i] = w;
    float4 xv = ((const float4*)g_x)[(size_t)g * 32 + lane];
    ((float4*)g_agg)[(size_t)i * 32 + lane] =
        make_float4(xv.x * w, xv.y * w, xv.z * w, xv.w * w);
}

// ---------------- edge pass 2: denom + unnormalized aggregation (warp/edge) -
__global__ void k_eagg(const void* __restrict__ idx, int sOff, int dOff, int E,
                       int sAdd, int dAdd, int base,
                       const float* __restrict__ as, const float* __restrict__ ad) {
    int e = (blockIdx.x * blockDim.x + threadIdx.x) >> 5;
    int lane = threadIdx.x & 31;
    if (e >= E) return;
    long long s, d;
    if (g_is64) {
        s = ((const long long*)idx)[sOff + e];
        d = ((const long long*)idx)[dOff + e];
    } else {
        s = ((const int*)idx)[sOff + e];
        d = ((const int*)idx)[dOff + e];
    }
    s += sAdd; d += dAdd;
    int di = (int)d - base;
    if ((unsigned)di >= (unsigned)HN) return;
    float ev = lrelu(as[s] + ad[d]);
    float w = __expf(ev - fdec(g_emax[di]));
    if (lane == 0) atomicAdd(&g_denom[di], w);
    float4 xv = ((const float4*)g_x)[(size_t)s * 32 + lane];
    atomicAdd(&((float4*)g_agg)[(size_t)di * 32 + lane],
              make_float4(xv.x * w, xv.y * w, xv.z * w, xv.w * w));
}

// ---------------- driver -----------------------------------------------------
extern "C" void kernel_launch(void* const* d_in, const int* in_sizes, int n_in,
                              void* d_out, int out_size) {
    const void*  edge   = d_in[0];
    const void*  paper  = d_in[1];
    const void*  author = d_in[2];
    const float* x_s = (const float*)d_in[3];
    const float* x_t = (const float*)d_in[4];
    const float* Ws  = (const float*)d_in[5];
    const float* bs  = (const float*)d_in[6];
    const float* Wt  = (const float*)d_in[7];
    const float* bt  = (const float*)d_in[8];
    const float* W1  = (const float*)d_in[9];
    const float* a1s = (const float*)d_in[10];
    const float* a1d = (const float*)d_in[11];
    const float* W2  = (const float*)d_in[12];
    const float* a2s = (const float*)d_in[13];
    const float* a2d = (const float*)d_in[14];
    float* out = (float*)d_out;

    const int E0 = in_sizes[0] / 2;   // bipartite
    const int E1 = in_sizes[1] / 2;   // paper
    const int E2 = in_sizes[2] / 2;   // author

    float* gx;     cudaGetSymbolAddress((void**)&gx,  g_x);
    float* gagg;   cudaGetSymbolAddress((void**)&gagg, g_agg);
    float *gas1, *gad1, *gas2, *gad2;
    cudaGetSymbolAddress((void**)&gas1, g_as1);
    cudaGetSymbolAddress((void**)&gad1, g_ad1);
    cudaGetSymbolAddress((void**)&gas2, g_as2);
    cudaGetSymbolAddress((void**)&gad2, g_ad2);
    float* gden;   cudaGetSymbolAddress((void**)&gden, g_denom);

    const int GEMM_BLKS = NS / 25;                 // 2000 (rows always 50000)
    const int TB = 256;
    const int EB0 = (E0 + TB - 1) / TB;
    const int EB1 = (E1 + TB - 1) / TB;
    const int EB2 = (E2 + TB - 1) / TB;
    const int WEB0 = (E0 * 32 + TB - 1) / TB;      // warp-per-edge grids
    const int WEB1 = (E1 * 32 + TB - 1) / TB;
    const int WEB2 = (E2 * 32 + TB - 1) / TB;
    const int NB   = (HN + TB - 1) / TB;
    const int WNB  = (HN * 32 + TB - 1) / TB;
    const int ATTB = (NN * 32 + TB - 1) / TB;

    k_detect<<<1, 32>>>((const int*)edge);
    k_wvec<<<1, 128>>>(W1, a1s, a1d, W2, a2s, a2d);

    // input transforms: x = [x_s@Ws^T+bs ; x_t@Wt^T+bt]
    k_gemm<<<GEMM_BLKS, 128>>>(x_s, Ws, bs, nullptr, gx, 0);
    k_gemm<<<GEMM_BLKS, 128>>>(x_t, Wt, bt, nullptr, gx + (size_t)NS * D, 0);

    k_att<<<ATTB, TB>>>();

    // ---- conv1: dst in [NS, NN). edges: (edge0 -> edge1+NS), author ----
    k_self1<<<NB, TB>>>(NS, gas1, gad1);
    k_emax<<<EB0, TB>>>(edge,   0,  E0, E0, 0,  NS, NS, gas1, gad1);
    k_emax<<<EB2, TB>>>(author, 0,  E2, E2, 0,  0,  NS, gas1, gad1);
    k_self2<<<WNB, TB>>>(NS, gas1, gad1);
    k_eagg<<<WEB0, TB>>>(edge,   0,  E0, E0, 0,  NS, NS, gas1, gad1);
    k_eagg<<<WEB2, TB>>>(author, 0,  E2, E2, 0,  0,  NS, gas1, gad1);
    // new_x_t = relu((agg/denom) @ W1^T), output rows [NS, NN)
    k_gemm<<<GEMM_BLKS, 128>>>(gagg, W1, nullptr, gden, out + (size_t)NS * D, 1);

    // ---- conv2: dst in [0, NS). edges: (edge1+NS -> edge0), paper ----
    k_self1<<<NB, TB>>>(0, gas2, gad2);
    k_emax<<<EB0, TB>>>(edge,  E0, 0,  E0, NS, 0, 0, gas2, gad2);
    k_emax<<<EB1, TB>>>(paper, 0,  E1, E1, 0,  0, 0, gas2, gad2);
    k_self2<<<WNB, TB>>>(0, gas2, gad2);
    k_eagg<<<WEB0, TB>>>(edge,  E0, 0,  E0, NS, 0, 0, gas2, gad2);
    k_eagg<<<WEB1, TB>>>(paper, 0,  E1, E1, 0,  0, 0, gas2, gad2);
    // new_x_s = relu((agg/denom) @ W2^T), output rows [0, NS)
    k_gemm<<<GEMM_BLKS, 128>>>(gagg, W2, nullptr, gden, out, 1);
}